// round 16
// baseline (speedup 1.0000x reference)
#include <cuda_runtime.h>
#include <cuda_bf16.h>
#include <cstdint>

// XLSTM social pooling as dense masked GEMM via mma.sync (HMMA bf16).
//
// Grid = 256 CTAs (64 batches x 2 i-halves x 2 h-halves), 512 threads / 16 warps,
// __launch_bounds__(512, 2) -> 2 CTAs/SM = 32 warps/SM (regs <= 64, smem 72KB x2).
// Per CTA: D[i(128), h(64)] = sum_{k=0..511} mask[i, j=k%256] * Hslice[k, h]
//   k<256: B = bf16_hi(H), k>=256: B = bf16_lo residual (same mask bits).
// Warp (wi 0..3, wh 0..3): tile 32i x 16h, full K=512. One ldsm4t + 4 mma per
// step; A fragments synthesized once per 16-j block, reused for hi+lo halves.

#define NA   256
#define NB   64
#define SEQL 20
#define HID  128

#define THREADS 512

#define PS_OFF   0                    // float2[256]
#define CNT_OFF  2048                 // float[128]
#define MSK_OFF  2560                 // u32[128][8]
#define H_OFF    8192                 // bf16[512][64], 128B rows, swizzled (64KB)
#define SMEM_BYTES (H_OFF + 512 * 128)

__device__ __forceinline__ uint32_t smem_u32(const void* p) {
    uint32_t a;
    asm("{ .reg .u64 t; cvta.to.shared.u64 t, %1; cvt.u32.u64 %0, t; }" : "=r"(a) : "l"(p));
    return a;
}

__device__ __forceinline__ void ldsm4t(uint32_t& r0, uint32_t& r1, uint32_t& r2,
                                       uint32_t& r3, uint32_t addr) {
    asm volatile("ldmatrix.sync.aligned.m8n8.x4.trans.shared.b16 {%0,%1,%2,%3}, [%4];"
                 : "=r"(r0), "=r"(r1), "=r"(r2), "=r"(r3) : "r"(addr));
}

__device__ __forceinline__ void mma_bf16(float* c, const uint32_t* a,
                                         uint32_t b0, uint32_t b1) {
    asm volatile(
        "mma.sync.aligned.m16n8k16.row.col.f32.bf16.bf16.f32 "
        "{%0,%1,%2,%3}, {%4,%5,%6,%7}, {%8,%9}, {%0,%1,%2,%3};"
        : "+f"(c[0]), "+f"(c[1]), "+f"(c[2]), "+f"(c[3])
        : "r"(a[0]), "r"(a[1]), "r"(a[2]), "r"(a[3]), "r"(b0), "r"(b1));
}

// 2 mask bits -> packed bf16x2 {1.0 or 0, 1.0 or 0}
__device__ __forceinline__ uint32_t bits2bf(uint32_t w, int sh) {
    const uint32_t p = (w >> sh) & 3u;
    return (p & 1u) * 0x3F80u + (p & 2u) * 0x1FC00000u;
}

__global__ __launch_bounds__(THREADS, 2)
void social_pool_hmma(const float* __restrict__ hidden,
                      const float* __restrict__ pos,
                      const float* __restrict__ radius_ptr,
                      float* __restrict__ out)
{
    extern __shared__ char smem[];
    const uint32_t sb = smem_u32(smem);
    float2*   ps   = (float2*)(smem + PS_OFF);
    float*    cnts = (float*)(smem + CNT_OFF);
    uint32_t* msk  = (uint32_t*)(smem + MSK_OFF);   // [128][8]

    const int tid  = threadIdx.x;
    const int wid  = tid >> 5;
    const int lane = tid & 31;
    const int b     = blockIdx.x >> 2;
    const int ihalf = (blockIdx.x >> 1) & 1;
    const int hhalf = blockIdx.x & 1;

    // --- stage positions (last timestep): threads 0..255 ---
    if (tid < NA) {
        const float* pp = pos + ((size_t)(tid * NB + b) * SEQL + (SEQL - 1)) * 2;
        ps[tid] = make_float2(pp[0], pp[1]);
    }
    __syncthreads();

    const float r  = *radius_ptr;
    const float r2 = r * r;

    // --- mask bitmasks + counts: warp w -> i-local rows [w*8, w*8+8) ---
    {
        float2 pjr[8];
        #pragma unroll
        for (int g2 = 0; g2 < 8; g2++) pjr[g2] = ps[g2 * 32 + lane];

        #pragma unroll
        for (int k = 0; k < 8; k++) {
            const int il = wid * 8 + k;
            const int ig = ihalf * 128 + il;
            const float2 pi = ps[ig];
            int cnt = 0;
            #pragma unroll
            for (int g2 = 0; g2 < 8; g2++) {
                const int jg = g2 * 32 + lane;
                const float dx = pi.x - pjr[g2].x;
                const float dy = pi.y - pjr[g2].y;
                const bool ok = (dx * dx + dy * dy <= r2) && (jg != ig);
                const unsigned bm = __ballot_sync(0xffffffffu, ok);
                cnt += __popc(bm);
                if (lane == 0) msk[il * 8 + g2] = bm;
            }
            if (lane == 0) cnts[il] = 1.0f / fmaxf((float)cnt, 1.0f);
        }
    }

    // --- stage H slice hi/lo bf16, swizzled 128B rows ---
    // 512 threads: 16 threads per j-row (64 cols / 4), 32 rows per iter, 8 iters
    #pragma unroll
    for (int it = 0; it < 8; it++) {
        const int j  = it * 32 + (tid >> 4);
        const int c4 = tid & 15;                      // float4 index in 64 cols
        const float4 v = *(const float4*)
            (hidden + ((size_t)(j * NB + b) * SEQL + (SEQL - 1)) * HID
                    + hhalf * 64 + c4 * 4);

        const __nv_bfloat162 h01 = __float22bfloat162_rn(make_float2(v.x, v.y));
        const __nv_bfloat162 h23 = __float22bfloat162_rn(make_float2(v.z, v.w));
        const float2 b01 = __bfloat1622float2(h01);
        const float2 b23 = __bfloat1622float2(h23);
        const __nv_bfloat162 l01 =
            __float22bfloat162_rn(make_float2(v.x - b01.x, v.y - b01.y));
        const __nv_bfloat162 l23 =
            __float22bfloat162_rn(make_float2(v.z - b23.x, v.w - b23.y));

        const uint32_t col = ((uint32_t)(c4 * 8)) ^ (((uint32_t)(j & 7)) << 4);
        uint2 hv, lv;
        hv.x = *(const uint32_t*)&h01;  hv.y = *(const uint32_t*)&h23;
        lv.x = *(const uint32_t*)&l01;  lv.y = *(const uint32_t*)&l23;
        *(uint2*)(smem + H_OFF + (size_t)j * 128 + col) = hv;
        *(uint2*)(smem + H_OFF + (size_t)(j + 256) * 128 + col) = lv;
    }
    __syncthreads();

    // --- GEMM: warp (wi 0..3, wh 0..3) -> tile 32i x 16h, K=512 ---
    const int wh = wid & 3;
    const int wi = wid >> 2;
    const int ibase = wi * 32, hbase = wh * 16;
    const int g = lane >> 2, t = lane & 3;
    const int lr = lane & 7, lmi = lane >> 3;

    const int rowoff = (lmi & 1) * 8 + lr;            // j row offset within 16
    const uint32_t colb =
        ((uint32_t)((hbase + (lmi >> 1) * 8) * 2)) ^ (((uint32_t)lr) << 4);
    const uint32_t baddr = sb + H_OFF + (uint32_t)rowoff * 128 + colb;

    float acc[2][2][4];
    #pragma unroll
    for (int mt = 0; mt < 2; mt++)
        #pragma unroll
        for (int nt = 0; nt < 2; nt++)
            #pragma unroll
            for (int c = 0; c < 4; c++) acc[mt][nt][c] = 0.0f;

    // step s = 0..31: jblk = s>>1, half = s&1; row base = half*256 + jblk*16
    uint32_t a[2][4];
    #pragma unroll
    for (int s = 0; s < 32; s++) {
        const int jblk = s >> 1;
        const int half = s & 1;
        const uint32_t rbase = (uint32_t)(half * 256 + jblk * 16) * 128;

        uint32_t bf[4];
        ldsm4t(bf[0], bf[1], bf[2], bf[3], baddr + rbase);

        if (half == 0) {
            const int jw = jblk >> 1;
            const int sh = ((jblk & 1) << 4) + 2 * t;
            #pragma unroll
            for (int mt = 0; mt < 2; mt++) {
                const int r0 = ibase + mt * 16 + g;
                const uint32_t w0 = msk[r0 * 8 + jw];
                const uint32_t w1 = msk[(r0 + 8) * 8 + jw];
                a[mt][0] = bits2bf(w0, sh);
                a[mt][1] = bits2bf(w1, sh);
                a[mt][2] = bits2bf(w0, sh + 8);
                a[mt][3] = bits2bf(w1, sh + 8);
            }
        }

        #pragma unroll
        for (int mt = 0; mt < 2; mt++) {
            mma_bf16(acc[mt][0], a[mt], bf[0], bf[1]);
            mma_bf16(acc[mt][1], a[mt], bf[2], bf[3]);
        }
    }

    // --- epilogue: scale by 1/count, write out ---
    #pragma unroll
    for (int mt = 0; mt < 2; mt++) {
        const int il0 = ibase + mt * 16 + g;
        const float s0 = cnts[il0];
        const float s1 = cnts[il0 + 8];
        const int ig0 = ihalf * 128 + il0;
        #pragma unroll
        for (int nt = 0; nt < 2; nt++) {
            const int h = hhalf * 64 + hbase + nt * 8 + 2 * t;
            float2 v0 = make_float2(acc[mt][nt][0] * s0, acc[mt][nt][1] * s0);
            float2 v1 = make_float2(acc[mt][nt][2] * s1, acc[mt][nt][3] * s1);
            *(float2*)(out + ((size_t)ig0 * NB + b) * HID + h) = v0;
            *(float2*)(out + ((size_t)(ig0 + 8) * NB + b) * HID + h) = v1;
        }
    }
}

extern "C" void kernel_launch(void* const* d_in, const int* in_sizes, int n_in,
                              void* d_out, int out_size)
{
    const float* hidden = (const float*)d_in[0];   // (256,64,20,128) f32
    const float* pos    = (const float*)d_in[1];   // (256,64,20,2)  f32
    const float* radius = (const float*)d_in[2];   // scalar f32
    float* out = (float*)d_out;                    // (256,64,128)   f32

    cudaFuncSetAttribute(social_pool_hmma,
                         cudaFuncAttributeMaxDynamicSharedMemorySize,
                         SMEM_BYTES);

    social_pool_hmma<<<NB * 4, THREADS, SMEM_BYTES>>>(hidden, pos, radius, out);
}

// round 17
// speedup vs baseline: 1.2959x; 1.2959x over previous
#include <cuda_runtime.h>
#include <cuda_bf16.h>
#include <cstdint>

// XLSTM social pooling as dense masked GEMM via mma.sync (HMMA bf16).
//
// Grid = 128 CTAs (64 batches x 2 i-halves), 1024 threads / 32 warps, 1 CTA/SM.
//   D[i(128), h(128)] = sum_{k=0..511} A[i,k] * B[k,h]
//   k<256: B = bf16_hi(H), k>=256: B = bf16_lo residual; A = mask (same both).
// NEW vs R16: mask materialized as bf16 tile [128][256] in smem; A fragments
// come from ldmatrix.x4 (non-trans) instead of per-warp ALU synthesis (which
// was 37.5% alu chip-wide). Warp (wi 0..3, wh 0..7): tile 32i x 16h, K=512.

#define NA   256
#define NB   64
#define SEQL 20
#define HID  128

#define THREADS 1024

#define PS_OFF   0                        // float2[256]           2KB
#define CNT_OFF  2048                     // float[128]            512B
#define MBF_OFF  4096                     // bf16[128][256] mask   64KB (512B rows)
#define H_OFF    (MBF_OFF + 65536)        // bf16[512][128] hi/lo  128KB (256B rows)
#define SMEM_BYTES (H_OFF + 512 * 256)

__device__ __forceinline__ uint32_t smem_u32(const void* p) {
    uint32_t a;
    asm("{ .reg .u64 t; cvta.to.shared.u64 t, %1; cvt.u32.u64 %0, t; }" : "=r"(a) : "l"(p));
    return a;
}

__device__ __forceinline__ void ldsm4(uint32_t& r0, uint32_t& r1, uint32_t& r2,
                                      uint32_t& r3, uint32_t addr) {
    asm volatile("ldmatrix.sync.aligned.m8n8.x4.shared.b16 {%0,%1,%2,%3}, [%4];"
                 : "=r"(r0), "=r"(r1), "=r"(r2), "=r"(r3) : "r"(addr));
}

__device__ __forceinline__ void ldsm4t(uint32_t& r0, uint32_t& r1, uint32_t& r2,
                                       uint32_t& r3, uint32_t addr) {
    asm volatile("ldmatrix.sync.aligned.m8n8.x4.trans.shared.b16 {%0,%1,%2,%3}, [%4];"
                 : "=r"(r0), "=r"(r1), "=r"(r2), "=r"(r3) : "r"(addr));
}

__device__ __forceinline__ void mma_bf16(float* c, const uint32_t* a,
                                         uint32_t b0, uint32_t b1) {
    asm volatile(
        "mma.sync.aligned.m16n8k16.row.col.f32.bf16.bf16.f32 "
        "{%0,%1,%2,%3}, {%4,%5,%6,%7}, {%8,%9}, {%0,%1,%2,%3};"
        : "+f"(c[0]), "+f"(c[1]), "+f"(c[2]), "+f"(c[3])
        : "r"(a[0]), "r"(a[1]), "r"(a[2]), "r"(a[3]), "r"(b0), "r"(b1));
}

__global__ __launch_bounds__(THREADS, 1)
void social_pool_hmma(const float* __restrict__ hidden,
                      const float* __restrict__ pos,
                      const float* __restrict__ radius_ptr,
                      float* __restrict__ out)
{
    extern __shared__ char smem[];
    const uint32_t sb = smem_u32(smem);
    float2* ps   = (float2*)(smem + PS_OFF);
    float*  cnts = (float*)(smem + CNT_OFF);

    const int tid  = threadIdx.x;
    const int wid  = tid >> 5;
    const int lane = tid & 31;
    const int b     = blockIdx.x >> 1;
    const int ihalf = blockIdx.x & 1;

    // --- stage positions (last timestep): threads 0..255 ---
    if (tid < NA) {
        const float* pp = pos + ((size_t)(tid * NB + b) * SEQL + (SEQL - 1)) * 2;
        ps[tid] = make_float2(pp[0], pp[1]);
    }
    __syncthreads();

    const float r  = *radius_ptr;
    const float r2 = r * r;

    // --- mask: ballots -> counts + bf16 mask tile (swizzled 512B rows) ---
    // warp w -> i-local rows [w*4, w*4+4)
    {
        float2 pjr[8];
        #pragma unroll
        for (int g2 = 0; g2 < 8; g2++) pjr[g2] = ps[g2 * 32 + lane];

        #pragma unroll
        for (int k = 0; k < 4; k++) {
            const int il = wid * 4 + k;
            const int ig = ihalf * 128 + il;
            const float2 pi = ps[ig];
            const uint32_t rowbase = MBF_OFF + (uint32_t)il * 512;
            const uint32_t sw = ((uint32_t)(il & 7)) << 4;
            int cnt = 0;
            #pragma unroll
            for (int g2 = 0; g2 < 8; g2++) {
                const int jg = g2 * 32 + lane;
                const float dx = pi.x - pjr[g2].x;
                const float dy = pi.y - pjr[g2].y;
                const bool ok = (dx * dx + dy * dy <= r2) && (jg != ig);
                const unsigned bm = __ballot_sync(0xffffffffu, ok);
                cnt += __popc(bm);
                const uint32_t off = ((uint32_t)(jg * 2)) ^ sw;
                *(uint16_t*)(smem + rowbase + off) = ok ? (uint16_t)0x3F80 : (uint16_t)0;
            }
            if (lane == 0) cnts[il] = 1.0f / fmaxf((float)cnt, 1.0f);
        }
    }

    // --- stage H hi/lo bf16, swizzled 256B rows ---
    // 1024 threads: 32 threads per j-row, 32 rows/iter, 8 iters over 256 rows
    #pragma unroll
    for (int it = 0; it < 8; it++) {
        const int j  = it * 32 + (tid >> 5);
        const int c4 = lane;                          // float4 index in 128 cols
        const float4 v = *(const float4*)
            (hidden + ((size_t)(j * NB + b) * SEQL + (SEQL - 1)) * HID + c4 * 4);

        const __nv_bfloat162 h01 = __float22bfloat162_rn(make_float2(v.x, v.y));
        const __nv_bfloat162 h23 = __float22bfloat162_rn(make_float2(v.z, v.w));
        const float2 b01 = __bfloat1622float2(h01);
        const float2 b23 = __bfloat1622float2(h23);
        const __nv_bfloat162 l01 =
            __float22bfloat162_rn(make_float2(v.x - b01.x, v.y - b01.y));
        const __nv_bfloat162 l23 =
            __float22bfloat162_rn(make_float2(v.z - b23.x, v.w - b23.y));

        const uint32_t col = ((uint32_t)(c4 * 8)) ^ (((uint32_t)(j & 7)) << 4);
        uint2 hv, lv;
        hv.x = *(const uint32_t*)&h01;  hv.y = *(const uint32_t*)&h23;
        lv.x = *(const uint32_t*)&l01;  lv.y = *(const uint32_t*)&l23;
        *(uint2*)(smem + H_OFF + (size_t)j * 256 + col) = hv;
        *(uint2*)(smem + H_OFF + (size_t)(j + 256) * 256 + col) = lv;
    }
    __syncthreads();

    // --- GEMM: warp (wi 0..3, wh 0..7) -> tile 32i x 16h, K=512 ---
    const int wh = wid & 7;
    const int wi = wid >> 3;
    const int ibase = wi * 32, hbase = wh * 16;
    const int g = lane >> 2, t = lane & 3;
    const int lr = lane & 7, lmi = lane >> 3;

    // B address (validated R13 mapping, 256B rows)
    const int rowoff = (lmi & 1) * 8 + lr;
    const uint32_t colb =
        ((uint32_t)((hbase + (lmi >> 1) * 8) * 2)) ^ (((uint32_t)lr) << 4);
    const uint32_t baddr = sb + H_OFF + (uint32_t)rowoff * 256 + colb;

    // A ldmatrix lane mapping: matrices {rows g, rows g+8} x {k0-7, k8-15}
    const int arow_lo = (lane & 15);                  // row within 16 (lanes 0-15)
    const uint32_t aq16 = ((uint32_t)(lane >> 4)) * 16u;  // +16B for k 8-15 half
    // per-mt row and its swizzle
    const int arow0 = ibase + arow_lo;                // mt = 0
    const int arow1 = ibase + 16 + arow_lo;           // mt = 1
    const uint32_t abase0 = sb + MBF_OFF + (uint32_t)arow0 * 512;
    const uint32_t abase1 = sb + MBF_OFF + (uint32_t)arow1 * 512;
    const uint32_t asw0 = ((uint32_t)(arow0 & 7)) << 4;
    const uint32_t asw1 = ((uint32_t)(arow1 & 7)) << 4;

    float acc[2][2][4];
    #pragma unroll
    for (int mt = 0; mt < 2; mt++)
        #pragma unroll
        for (int nt = 0; nt < 2; nt++)
            #pragma unroll
            for (int c = 0; c < 4; c++) acc[mt][nt][c] = 0.0f;

    uint32_t a[2][4];
    #pragma unroll
    for (int s = 0; s < 32; s++) {
        const int jblk = s >> 1;
        const int half = s & 1;

        if (half == 0) {
            const uint32_t jcol = (uint32_t)(jblk * 32) + aq16;
            ldsm4(a[0][0], a[0][1], a[0][2], a[0][3], abase0 + (jcol ^ asw0));
            ldsm4(a[1][0], a[1][1], a[1][2], a[1][3], abase1 + (jcol ^ asw1));
        }

        uint32_t bf[4];
        const uint32_t rbase = (uint32_t)(half * 256 + jblk * 16) * 256;
        ldsm4t(bf[0], bf[1], bf[2], bf[3], baddr + rbase);

        #pragma unroll
        for (int mt = 0; mt < 2; mt++) {
            mma_bf16(acc[mt][0], a[mt], bf[0], bf[1]);
            mma_bf16(acc[mt][1], a[mt], bf[2], bf[3]);
        }
    }

    // --- epilogue: scale by 1/count, write out ---
    #pragma unroll
    for (int mt = 0; mt < 2; mt++) {
        const int il0 = ibase + mt * 16 + g;
        const float s0 = cnts[il0];
        const float s1 = cnts[il0 + 8];
        const int ig0 = ihalf * 128 + il0;
        #pragma unroll
        for (int nt = 0; nt < 2; nt++) {
            const int h = hbase + nt * 8 + 2 * t;
            float2 v0 = make_float2(acc[mt][nt][0] * s0, acc[mt][nt][1] * s0);
            float2 v1 = make_float2(acc[mt][nt][2] * s1, acc[mt][nt][3] * s1);
            *(float2*)(out + ((size_t)ig0 * NB + b) * HID + h) = v0;
            *(float2*)(out + ((size_t)(ig0 + 8) * NB + b) * HID + h) = v1;
        }
    }
}

extern "C" void kernel_launch(void* const* d_in, const int* in_sizes, int n_in,
                              void* d_out, int out_size)
{
    const float* hidden = (const float*)d_in[0];   // (256,64,20,128) f32
    const float* pos    = (const float*)d_in[1];   // (256,64,20,2)  f32
    const float* radius = (const float*)d_in[2];   // scalar f32
    float* out = (float*)d_out;                    // (256,64,128)   f32

    cudaFuncSetAttribute(social_pool_hmma,
                         cudaFuncAttributeMaxDynamicSharedMemorySize,
                         SMEM_BYTES);

    social_pool_hmma<<<NB * 2, THREADS, SMEM_BYTES>>>(hidden, pos, radius, out);
}